// round 13
// baseline (speedup 1.0000x reference)
#include <cuda_runtime.h>
#include <cuda_fp16.h>
#include <math.h>
#include <stdint.h>

// ---------------------------------------------------------------------------
// Problem constants
// ---------------------------------------------------------------------------
constexpr int BATCH = 8192, INPUT = 4096, HIDDEN = 4096, CLASSES = 1000;
constexpr int NPAD = 1024;
constexpr int KDIM = 4096;
constexpr int BM = 128, BN = 128, BK = 64;
constexpr int NITER = KDIM / BK;           // 64
constexpr int STRIDE = 144;                // padded smem row bytes (128 data + 16 pad)
constexpr int TILE_B = 128 * STRIDE;       // 18432 bytes per tile
constexpr int STAGE_B = 4 * TILE_B;        // 73728 (A0,B0,A1,B1)
constexpr int NSTAGES = 3;
constexpr int DYN_SMEM = NSTAGES * STAGE_B;  // 221184
constexpr int GTHREADS = 512;              // 16 warps -> 4 warps/SMSP

// ---------------------------------------------------------------------------
// Scratch (__device__ globals; allocation-free)
// ---------------------------------------------------------------------------
__device__ __align__(1024) __half g_x_s[2][(size_t)BATCH * INPUT];
__device__ __align__(1024) __half g_w1_s[2][(size_t)HIDDEN * INPUT];
__device__ __align__(1024) __half g_w2_s[2][(size_t)NPAD * INPUT];
__device__ __align__(1024) __half g_h_s[2][(size_t)BATCH * HIDDEN];
__device__ __align__(1024) float g_logits[(size_t)BATCH * NPAD];

// ---------------------------------------------------------------------------
// PTX helpers (sm_80-level only: cp.async, ldmatrix, mma.sync)
// ---------------------------------------------------------------------------
__device__ __forceinline__ uint32_t smem_u32(const void* p) {
    uint32_t a;
    asm("{ .reg .u64 t; cvta.to.shared.u64 t, %1; cvt.u32.u64 %0, t; }"
        : "=r"(a) : "l"(p));
    return a;
}
__device__ __forceinline__ void cp_async16(uint32_t dst, const void* src) {
    asm volatile("cp.async.cg.shared.global [%0], [%1], 16;"
                 :: "r"(dst), "l"(src) : "memory");
}
__device__ __forceinline__ void cp_commit() {
    asm volatile("cp.async.commit_group;" ::: "memory");
}
__device__ __forceinline__ void cp_wait0() {
    asm volatile("cp.async.wait_group 0;" ::: "memory");
}
__device__ __forceinline__ void cp_wait1() {
    asm volatile("cp.async.wait_group 1;" ::: "memory");
}
__device__ __forceinline__ void ldmatrix_x4(uint32_t& r0, uint32_t& r1,
                                            uint32_t& r2, uint32_t& r3, uint32_t a) {
    asm volatile("ldmatrix.sync.aligned.m8n8.x4.shared.b16 {%0,%1,%2,%3}, [%4];"
                 : "=r"(r0), "=r"(r1), "=r"(r2), "=r"(r3) : "r"(a));
}
__device__ __forceinline__ void mma_f16(float* d, const uint32_t* a, const uint32_t* b) {
    asm volatile(
        "mma.sync.aligned.m16n8k16.row.col.f32.f16.f16.f32 "
        "{%0,%1,%2,%3}, {%4,%5,%6,%7}, {%8,%9}, {%0,%1,%2,%3};"
        : "+f"(d[0]), "+f"(d[1]), "+f"(d[2]), "+f"(d[3])
        : "r"(a[0]), "r"(a[1]), "r"(a[2]), "r"(a[3]), "r"(b[0]), "r"(b[1]));
}

__device__ __forceinline__ uint32_t pack_f16(__half a, __half b) {
    __half2 t{a, b};
    uint32_t r;
    memcpy(&r, &t, 4);
    return r;
}
__device__ __forceinline__ void split2(float v, __half& h, __half& l) {
    h = __float2half_rn(v);
    l = __float2half_rn(v - __half2float(h));
}

// ---------------------------------------------------------------------------
// Split kernels (fp32 -> 2x fp16 components)
// ---------------------------------------------------------------------------
__global__ __launch_bounds__(256)
void split2_kernel(const float4* __restrict__ in, int n4,
                   __half* __restrict__ h, __half* __restrict__ l) {
    int i = blockIdx.x * blockDim.x + threadIdx.x;
    if (i >= n4) return;
    float4 v = in[i];
    __half h0, h1, h2, h3, l0, l1, l2, l3;
    split2(v.x, h0, l0);
    split2(v.y, h1, l1);
    split2(v.z, h2, l2);
    split2(v.w, h3, l3);
    ((uint2*)h)[i] = make_uint2(pack_f16(h0, h1), pack_f16(h2, h3));
    ((uint2*)l)[i] = make_uint2(pack_f16(l0, l1), pack_f16(l2, l3));
}

__global__ __launch_bounds__(256)
void split2_pad_kernel(const float4* __restrict__ in, int n4_total,
                       __half* __restrict__ h, __half* __restrict__ l) {
    int i = blockIdx.x * blockDim.x + threadIdx.x;
    if (i >= n4_total) return;
    int row = i >> 10;  // INPUT/4 = 1024 float4 per row
    float4 v = (row < CLASSES) ? in[i] : make_float4(0.f, 0.f, 0.f, 0.f);
    __half h0, h1, h2, h3, l0, l1, l2, l3;
    split2(v.x, h0, l0);
    split2(v.y, h1, l1);
    split2(v.z, h2, l2);
    split2(v.w, h3, l3);
    ((uint2*)h)[i] = make_uint2(pack_f16(h0, h1), pack_f16(h2, h3));
    ((uint2*)l)[i] = make_uint2(pack_f16(l0, l1), pack_f16(l2, l3));
}

// ---------------------------------------------------------------------------
// Pipelined mma.sync fp16 GEMM, 2-way split, 3 products, DUAL accumulators:
//   acc  <- hi*hi ; acc2 <- hi*lo + lo*hi      (lo*lo dropped, ~2^-22)
// 128x128 CTA tile, BK=64, 3 buffers, 512 threads (4 warps/SMSP), 32x32 warp
// tiles. Cross-barrier kh0-fragment prefetch: pipeline wait moved to iter END
// (wait0 + barrier), then each warp prefetches next iter's kh0 A/B fragments
// from the already-resident next buffer, so post-barrier MMAs start with zero
// LDSM dependency head.
// MODE 0: out = relu(C + bias), re-split to 2 fp16 arrays (ld = HIDDEN)
// MODE 1: out = C + bias (fp32, ld = NPAD, bias guarded to biasN)
// ---------------------------------------------------------------------------
template <int MODE>
__global__ __launch_bounds__(GTHREADS, 1)
void gemm_kernel(const __half* __restrict__ A0,
                 const __half* __restrict__ A1,
                 const __half* __restrict__ B0,
                 const __half* __restrict__ B1,
                 const float* __restrict__ bias, int biasN,
                 __half* __restrict__ o_hi,
                 __half* __restrict__ o_lo,
                 float* __restrict__ o_f32) {
    extern __shared__ __align__(128) char smem[];
    const uint32_t smem_u = smem_u32(smem);

    const int tid = threadIdx.x;
    const int lane = tid & 31;
    const int wid = tid >> 5;       // 0..15
    const int warpRow = wid >> 2;   // 0..3 -> 32 rows each
    const int warpCol = wid & 3;    // 0..3 -> 32 cols each
    const int blockM = blockIdx.y * BM;
    const int blockN = blockIdx.x * BN;

    constexpr size_t K2 = (size_t)KDIM * 2;

    // ---- loader: 512 threads, 8 cp.async each (2 rows x 4 matrices) ----
    const int lrow = tid >> 3;      // 0..63
    const int lch = tid & 7;        // 0..7 (16B chunk within 128B row)
    const char* gp[4];
    gp[0] = (const char*)A0 + (size_t)(blockM + lrow) * K2 + lch * 16;
    gp[1] = (const char*)B0 + (size_t)(blockN + lrow) * K2 + lch * 16;
    gp[2] = (const char*)A1 + (size_t)(blockM + lrow) * K2 + lch * 16;
    gp[3] = (const char*)B1 + (size_t)(blockN + lrow) * K2 + lch * 16;
    const uint32_t sdst0 = lrow * STRIDE + lch * 16;

    auto load_stage = [&](int bufb) {
        const uint32_t sb = smem_u + bufb * STAGE_B + sdst0;
        #pragma unroll
        for (int mc = 0; mc < 4; mc++) {
            const char* g = gp[mc];
            cp_async16(sb + mc * TILE_B, g);
            cp_async16(sb + mc * TILE_B + 64 * STRIDE, g + (size_t)64 * K2);
            gp[mc] = g + BK * 2;   // advance K by BK elements
        }
        cp_commit();
    };

    float acc[2][4][4];   // main: hi*hi   (2 m16 tiles x 4 n8 tiles)
    float acc2[2][4][4];  // corrections: hi*lo + lo*hi
    #pragma unroll
    for (int mt = 0; mt < 2; mt++)
        #pragma unroll
        for (int nt = 0; nt < 4; nt++)
            #pragma unroll
            for (int e = 0; e < 4; e++) { acc[mt][nt][e] = 0.0f; acc2[mt][nt][e] = 0.0f; }

    // ldmatrix per-lane address components
    const int rA = ((lane >> 3) & 1) * 8 + (lane & 7);
    const int cA = (lane >> 4);
    const int rB = (lane >> 4) * 8 + (lane & 7);
    const int cB = (lane >> 3) & 1;

    auto ldAkh = [&](uint32_t (&dst)[2][2][4], uint32_t stage, int kh) {
        #pragma unroll
        for (int t = 0; t < 2; t++) {
            const uint32_t Abase = stage + (2 * t) * TILE_B;
            #pragma unroll
            for (int mt = 0; mt < 2; mt++) {
                uint32_t addr = Abase + (warpRow * 32 + mt * 16 + rA) * STRIDE +
                                (kh * 2 + cA) * 16;
                ldmatrix_x4(dst[t][mt][0], dst[t][mt][1], dst[t][mt][2], dst[t][mt][3], addr);
            }
        }
    };
    auto ldBkh = [&](uint32_t (&dst)[2][4][2], uint32_t stage, int kh) {
        #pragma unroll
        for (int t = 0; t < 2; t++) {
            const uint32_t Bbase = stage + (2 * t + 1) * TILE_B;
            #pragma unroll
            for (int pr = 0; pr < 2; pr++) {
                uint32_t addr = Bbase + (warpCol * 32 + pr * 16 + rB) * STRIDE +
                                (kh * 2 + cB) * 16;
                uint32_t r0, r1, r2, r3;
                ldmatrix_x4(r0, r1, r2, r3, addr);
                dst[t][pr * 2 + 0][0] = r0; dst[t][pr * 2 + 0][1] = r1;
                dst[t][pr * 2 + 1][0] = r2; dst[t][pr * 2 + 1][1] = r3;
            }
        }
    };
    auto mmaKh = [&](uint32_t (&aF)[2][2][4], uint32_t (&bF)[2][4][2]) {
        // grouped by product (r10 order: best measured)
        #pragma unroll
        for (int mt = 0; mt < 2; mt++)
            #pragma unroll
            for (int nt = 0; nt < 4; nt++)
                mma_f16(acc[mt][nt], aF[0][mt], bF[0][nt]);
        #pragma unroll
        for (int mt = 0; mt < 2; mt++)
            #pragma unroll
            for (int nt = 0; nt < 4; nt++)
                mma_f16(acc2[mt][nt], aF[0][mt], bF[1][nt]);
        #pragma unroll
        for (int mt = 0; mt < 2; mt++)
            #pragma unroll
            for (int nt = 0; nt < 4; nt++)
                mma_f16(acc2[mt][nt], aF[1][mt], bF[0][nt]);
    };

    // kh0 fragments for the NEXT iter, prefetched across the barrier
    uint32_t aP[2][2][4], bP[2][4][2];

    // prologue: stages 0,1 in flight; wait for stage 0, prefetch kh0 of it=0
    load_stage(0);
    load_stage(1);
    cp_wait1();            // stage 0 done (stage 1 may be pending)
    __syncthreads();
    ldAkh(aP, smem_u + 0 * STAGE_B, 0);
    ldBkh(bP, smem_u + 0 * STAGE_B, 0);

    for (int it = 0; it < NITER; it++) {
        const uint32_t stage = smem_u + (it % NSTAGES) * STAGE_B;

        // kh0: fragments already in registers (prefetched last iter)
        mmaKh(aP, bP);
        // kh1..kh3: load + mma inline
        #pragma unroll
        for (int kh = 1; kh < 4; kh++) {
            uint32_t aF[2][2][4];
            uint32_t bF[2][4][2];
            ldAkh(aF, stage, kh);
            ldBkh(bF, stage, kh);
            mmaKh(aF, bF);
        }

        if (it + 1 < NITER) {
            cp_wait0();        // stage it+1 fully arrived
            __syncthreads();   // cross-thread visibility + consume-complete
            // prefetch next iter's kh0 fragments (buffer (it+1)%3 is valid and
            // will NOT be overwritten by the load below)
            const uint32_t nstage = smem_u + ((it + 1) % NSTAGES) * STAGE_B;
            ldAkh(aP, nstage, 0);
            ldBkh(bP, nstage, 0);
            // refill buffer (it+2)%3 == (it-1)%3 (consumed at it-1; all warps
            // passed the barrier above)
            if (it + 2 < NITER) load_stage((it + 2) % NSTAGES);
        }
    }

    // ---- epilogue ----
    const int gr = lane >> 2;         // row within 8
    const int cc = (lane & 3) * 2;    // col pair

    #pragma unroll
    for (int mt = 0; mt < 2; mt++) {
        #pragma unroll
        for (int nt = 0; nt < 4; nt++) {
            float d[4];
            #pragma unroll
            for (int e = 0; e < 4; e++) d[e] = acc[mt][nt][e] + acc2[mt][nt][e];
            const int col = blockN + warpCol * 32 + nt * 8 + cc;
            const int row0 = blockM + warpRow * 32 + mt * 16 + gr;
            float bv0, bv1;
            if (MODE == 0) {
                bv0 = bias[col];
                bv1 = bias[col + 1];
            } else {
                bv0 = (col < biasN) ? bias[col] : 0.0f;
                bv1 = (col + 1 < biasN) ? bias[col + 1] : 0.0f;
            }
            if (MODE == 0) {
                #pragma unroll
                for (int h = 0; h < 2; h++) {
                    const int row = row0 + h * 8;
                    float v0 = fmaxf(d[2 * h + 0] + bv0, 0.0f);
                    float v1 = fmaxf(d[2 * h + 1] + bv1, 0.0f);
                    __half h0, l0, h1, l1;
                    split2(v0, h0, l0);
                    split2(v1, h1, l1);
                    size_t off = (size_t)row * HIDDEN + col;
                    *(uint32_t*)(o_hi + off) = pack_f16(h0, h1);
                    *(uint32_t*)(o_lo + off) = pack_f16(l0, l1);
                }
            } else {
                #pragma unroll
                for (int h = 0; h < 2; h++) {
                    const int row = row0 + h * 8;
                    float2 v;
                    v.x = d[2 * h + 0] + bv0;
                    v.y = d[2 * h + 1] + bv1;
                    *(float2*)(o_f32 + (size_t)row * NPAD + col) = v;
                }
            }
        }
    }
}

// ---------------------------------------------------------------------------
// Row softmax (reads NPAD-strided logits, first CLASSES cols)
// ---------------------------------------------------------------------------
__inline__ __device__ float warpMax(float v) {
    #pragma unroll
    for (int o = 16; o > 0; o >>= 1) v = fmaxf(v, __shfl_xor_sync(0xffffffffu, v, o));
    return v;
}
__inline__ __device__ float warpSum(float v) {
    #pragma unroll
    for (int o = 16; o > 0; o >>= 1) v += __shfl_xor_sync(0xffffffffu, v, o);
    return v;
}

__global__ __launch_bounds__(256)
void softmax_kernel(const float* __restrict__ logits, float* __restrict__ out) {
    const int row = blockIdx.x;
    const float* lp = logits + (size_t)row * NPAD;
    float* op = out + (size_t)row * CLASSES;

    const int tid = threadIdx.x, lane = tid & 31, warp = tid >> 5;
    __shared__ float red[8];

    float v[4];
    int idx[4], cnt = 0;
    for (int i = tid; i < CLASSES; i += 256) { v[cnt] = lp[i]; idx[cnt] = i; cnt++; }

    float m = -INFINITY;
    for (int t = 0; t < cnt; t++) m = fmaxf(m, v[t]);
    m = warpMax(m);
    if (lane == 0) red[warp] = m;
    __syncthreads();
    m = (lane < 8) ? red[lane] : -INFINITY;
    m = warpMax(m);
    m = __shfl_sync(0xffffffffu, m, 0);

    float s = 0.0f;
    for (int t = 0; t < cnt; t++) { v[t] = __expf(v[t] - m); s += v[t]; }
    s = warpSum(s);
    __syncthreads();
    if (lane == 0) red[warp] = s;
    __syncthreads();
    s = (lane < 8) ? red[lane] : 0.0f;
    s = warpSum(s);
    s = __shfl_sync(0xffffffffu, s, 0);

    const float inv = 1.0f / s;
    for (int t = 0; t < cnt; t++) op[idx[t]] = v[t] * inv;
}

// ---------------------------------------------------------------------------
// Host launch
// ---------------------------------------------------------------------------
extern "C" void kernel_launch(void* const* d_in, const int* in_sizes, int n_in,
                              void* d_out, int out_size) {
    const float* x  = (const float*)d_in[0];
    const float* w1 = (const float*)d_in[1];
    const float* b1 = (const float*)d_in[2];
    const float* w2 = (const float*)d_in[3];
    const float* b2 = (const float*)d_in[4];
    float* out = (float*)d_out;

    __half *xs, *w1s, *w2s, *hs;
    float* logits;
    cudaGetSymbolAddress((void**)&xs,  g_x_s);
    cudaGetSymbolAddress((void**)&w1s, g_w1_s);
    cudaGetSymbolAddress((void**)&w2s, g_w2_s);
    cudaGetSymbolAddress((void**)&hs,  g_h_s);
    cudaGetSymbolAddress((void**)&logits, g_logits);

    const size_t XN  = (size_t)BATCH * INPUT;
    const size_t W1N = (size_t)HIDDEN * INPUT;
    const size_t W2N = (size_t)NPAD * INPUT;
    const size_t HN  = (size_t)BATCH * HIDDEN;

    __half* x_c[2]  = {xs, xs + XN};
    __half* w1_c[2] = {w1s, w1s + W1N};
    __half* w2_c[2] = {w2s, w2s + W2N};
    __half* h_c[2]  = {hs, hs + HN};

    {
        int n4 = (int)(XN / 4);
        split2_kernel<<<(n4 + 255) / 256, 256>>>((const float4*)x, n4, x_c[0], x_c[1]);
    }
    {
        int n4 = (int)(W1N / 4);
        split2_kernel<<<(n4 + 255) / 256, 256>>>((const float4*)w1, n4, w1_c[0], w1_c[1]);
    }
    {
        int n4 = (int)(W2N / 4);
        split2_pad_kernel<<<(n4 + 255) / 256, 256>>>((const float4*)w2, n4, w2_c[0], w2_c[1]);
    }

    cudaFuncSetAttribute(gemm_kernel<0>, cudaFuncAttributeMaxDynamicSharedMemorySize, DYN_SMEM);
    cudaFuncSetAttribute(gemm_kernel<1>, cudaFuncAttributeMaxDynamicSharedMemorySize, DYN_SMEM);

    // GEMM1: hidden = relu(x @ w1^T + b1), re-split into 2 fp16 components
    {
        dim3 grid(HIDDEN / BN, BATCH / BM);
        gemm_kernel<0><<<grid, GTHREADS, DYN_SMEM>>>(
            x_c[0], x_c[1], w1_c[0], w1_c[1],
            b1, HIDDEN, h_c[0], h_c[1], nullptr);
    }
    // GEMM2: logits = hidden @ w2^T + b2 (fp32, NPAD-wide scratch)
    {
        dim3 grid(NPAD / BN, BATCH / BM);
        gemm_kernel<1><<<grid, GTHREADS, DYN_SMEM>>>(
            h_c[0], h_c[1], w2_c[0], w2_c[1],
            b2, CLASSES, nullptr, nullptr, logits);
    }
    softmax_kernel<<<BATCH, 256>>>(logits, out);
}

// round 14
// speedup vs baseline: 1.3717x; 1.3717x over previous
#include <cuda_runtime.h>
#include <cuda_fp16.h>
#include <math.h>
#include <stdint.h>

// ---------------------------------------------------------------------------
// Problem constants
// ---------------------------------------------------------------------------
constexpr int BATCH = 8192, INPUT = 4096, HIDDEN = 4096, CLASSES = 1000;
constexpr int NPAD = 1024;
constexpr int KDIM = 4096;
constexpr int BM = 128, BN = 128, BK = 64;
constexpr int NITER = KDIM / BK;           // 64
constexpr int STRIDE = 144;                // padded smem row bytes (128 data + 16 pad)
constexpr int TILE_B = 128 * STRIDE;       // 18432 bytes per tile
constexpr int STAGE_B = 4 * TILE_B;        // 73728 (A0,B0,A1,B1)
constexpr int NSTAGES = 3;
constexpr int DYN_SMEM = NSTAGES * STAGE_B;  // 221184
constexpr int GTHREADS = 512;              // 16 warps -> 4 warps/SMSP

// ---------------------------------------------------------------------------
// Scratch (__device__ globals; allocation-free)
// ---------------------------------------------------------------------------
__device__ __align__(1024) __half g_x_s[2][(size_t)BATCH * INPUT];
__device__ __align__(1024) __half g_w1_s[2][(size_t)HIDDEN * INPUT];
__device__ __align__(1024) __half g_w2_s[2][(size_t)NPAD * INPUT];
__device__ __align__(1024) __half g_h_s[2][(size_t)BATCH * HIDDEN];
__device__ __align__(1024) float g_logits[(size_t)BATCH * NPAD];

// ---------------------------------------------------------------------------
// PTX helpers (sm_80-level only: cp.async, ldmatrix, mma.sync)
// ---------------------------------------------------------------------------
__device__ __forceinline__ uint32_t smem_u32(const void* p) {
    uint32_t a;
    asm("{ .reg .u64 t; cvta.to.shared.u64 t, %1; cvt.u32.u64 %0, t; }"
        : "=r"(a) : "l"(p));
    return a;
}
__device__ __forceinline__ void cp_async16(uint32_t dst, const void* src) {
    asm volatile("cp.async.cg.shared.global [%0], [%1], 16;"
                 :: "r"(dst), "l"(src) : "memory");
}
__device__ __forceinline__ void cp_commit() {
    asm volatile("cp.async.commit_group;" ::: "memory");
}
__device__ __forceinline__ void cp_wait0() {
    asm volatile("cp.async.wait_group 0;" ::: "memory");
}
__device__ __forceinline__ void cp_wait1() {
    asm volatile("cp.async.wait_group 1;" ::: "memory");
}
__device__ __forceinline__ void ldmatrix_x4(uint32_t& r0, uint32_t& r1,
                                            uint32_t& r2, uint32_t& r3, uint32_t a) {
    asm volatile("ldmatrix.sync.aligned.m8n8.x4.shared.b16 {%0,%1,%2,%3}, [%4];"
                 : "=r"(r0), "=r"(r1), "=r"(r2), "=r"(r3) : "r"(a));
}
__device__ __forceinline__ void mma_f16(float* d, const uint32_t* a, const uint32_t* b) {
    asm volatile(
        "mma.sync.aligned.m16n8k16.row.col.f32.f16.f16.f32 "
        "{%0,%1,%2,%3}, {%4,%5,%6,%7}, {%8,%9}, {%0,%1,%2,%3};"
        : "+f"(d[0]), "+f"(d[1]), "+f"(d[2]), "+f"(d[3])
        : "r"(a[0]), "r"(a[1]), "r"(a[2]), "r"(a[3]), "r"(b[0]), "r"(b[1]));
}

__device__ __forceinline__ uint32_t pack_f16(__half a, __half b) {
    __half2 t{a, b};
    uint32_t r;
    memcpy(&r, &t, 4);
    return r;
}
__device__ __forceinline__ void split2(float v, __half& h, __half& l) {
    h = __float2half_rn(v);
    l = __float2half_rn(v - __half2float(h));
}

// ---------------------------------------------------------------------------
// Merged split kernel: one launch handles x, w1, w2 (w2 zero-padded to NPAD).
// Segments (in float4 chunks): [0, n4x) -> x ; [n4x, n4x+n4w1) -> w1 ;
// [n4x+n4w1, n4x+n4w1+n4w2p) -> w2 (rows >= CLASSES zero-filled).
// ---------------------------------------------------------------------------
__global__ __launch_bounds__(256)
void split2_all_kernel(const float4* __restrict__ x,
                       const float4* __restrict__ w1,
                       const float4* __restrict__ w2,
                       __half* __restrict__ xh, __half* __restrict__ xl,
                       __half* __restrict__ w1h, __half* __restrict__ w1l,
                       __half* __restrict__ w2h, __half* __restrict__ w2l,
                       int n4x, int n4w1, int n4w2p) {
    int i = blockIdx.x * blockDim.x + threadIdx.x;
    float4 v;
    __half* dh;
    __half* dl;
    int di;
    if (i < n4x) {
        v = x[i];
        dh = xh; dl = xl; di = i;
    } else if (i < n4x + n4w1) {
        di = i - n4x;
        v = w1[di];
        dh = w1h; dl = w1l;
    } else if (i < n4x + n4w1 + n4w2p) {
        di = i - n4x - n4w1;
        int row = di >> 10;  // INPUT/4 = 1024 float4 per row
        v = (row < CLASSES) ? w2[di] : make_float4(0.f, 0.f, 0.f, 0.f);
        dh = w2h; dl = w2l;
    } else {
        return;
    }
    __half h0, h1, h2, h3, l0, l1, l2, l3;
    split2(v.x, h0, l0);
    split2(v.y, h1, l1);
    split2(v.z, h2, l2);
    split2(v.w, h3, l3);
    ((uint2*)dh)[di] = make_uint2(pack_f16(h0, h1), pack_f16(h2, h3));
    ((uint2*)dl)[di] = make_uint2(pack_f16(l0, l1), pack_f16(l2, l3));
}

// ---------------------------------------------------------------------------
// Pipelined mma.sync fp16 GEMM, 2-way split, 3 products, DUAL accumulators:
//   acc  <- hi*hi ; acc2 <- hi*lo + lo*hi      (lo*lo dropped, ~2^-22)
// 128x128 CTA tile, BK=64, 3 stages + wait_group(1) (2-iter DMA lookahead),
// 512 threads (4 warps/SMSP), 32x32 warp tiles, products grouped
// (round-10 configuration: best measured, 3012.6us / tensor 64.9%).
// MODE 0: out = relu(C + bias), re-split to 2 fp16 arrays (ld = HIDDEN)
// MODE 1: out = C + bias (fp32, ld = NPAD, bias guarded to biasN)
// ---------------------------------------------------------------------------
template <int MODE>
__global__ __launch_bounds__(GTHREADS, 1)
void gemm_kernel(const __half* __restrict__ A0,
                 const __half* __restrict__ A1,
                 const __half* __restrict__ B0,
                 const __half* __restrict__ B1,
                 const float* __restrict__ bias, int biasN,
                 __half* __restrict__ o_hi,
                 __half* __restrict__ o_lo,
                 float* __restrict__ o_f32) {
    extern __shared__ __align__(128) char smem[];
    const uint32_t smem_u = smem_u32(smem);

    const int tid = threadIdx.x;
    const int lane = tid & 31;
    const int wid = tid >> 5;       // 0..15
    const int warpRow = wid >> 2;   // 0..3 -> 32 rows each
    const int warpCol = wid & 3;    // 0..3 -> 32 cols each
    const int blockM = blockIdx.y * BM;
    const int blockN = blockIdx.x * BN;

    constexpr size_t K2 = (size_t)KDIM * 2;

    // ---- loader: 512 threads, 8 cp.async each (2 rows x 4 matrices) ----
    const int lrow = tid >> 3;      // 0..63
    const int lch = tid & 7;        // 0..7 (16B chunk within 128B row)
    const char* gp[4];
    gp[0] = (const char*)A0 + (size_t)(blockM + lrow) * K2 + lch * 16;
    gp[1] = (const char*)B0 + (size_t)(blockN + lrow) * K2 + lch * 16;
    gp[2] = (const char*)A1 + (size_t)(blockM + lrow) * K2 + lch * 16;
    gp[3] = (const char*)B1 + (size_t)(blockN + lrow) * K2 + lch * 16;
    const uint32_t sdst0 = lrow * STRIDE + lch * 16;

    auto load_stage = [&](int bufb) {
        const uint32_t sb = smem_u + bufb * STAGE_B + sdst0;
        #pragma unroll
        for (int mc = 0; mc < 4; mc++) {
            const char* g = gp[mc];
            cp_async16(sb + mc * TILE_B, g);
            cp_async16(sb + mc * TILE_B + 64 * STRIDE, g + (size_t)64 * K2);
            gp[mc] = g + BK * 2;   // advance K by BK elements
        }
        cp_commit();
    };

    float acc[2][4][4];   // main: hi*hi   (2 m16 tiles x 4 n8 tiles)
    float acc2[2][4][4];  // corrections: hi*lo + lo*hi
    #pragma unroll
    for (int mt = 0; mt < 2; mt++)
        #pragma unroll
        for (int nt = 0; nt < 4; nt++)
            #pragma unroll
            for (int e = 0; e < 4; e++) { acc[mt][nt][e] = 0.0f; acc2[mt][nt][e] = 0.0f; }

    // ldmatrix per-lane address components
    const int rA = ((lane >> 3) & 1) * 8 + (lane & 7);
    const int cA = (lane >> 4);
    const int rB = (lane >> 4) * 8 + (lane & 7);
    const int cB = (lane >> 3) & 1;

    // prologue: stages 0, 1
    load_stage(0);
    load_stage(1);

    for (int it = 0; it < NITER; it++) {
        if (it + 1 < NITER) cp_wait1(); else cp_wait0();
        __syncthreads();
        // issue stage it+2 into buffer (it+2)%3 == (it-1)%3 (consumed at it-1;
        // safe: all warps passed the barrier above after finishing it-1)
        if (it + 2 < NITER) load_stage((it + 2) % NSTAGES);

        const uint32_t stage = smem_u + (it % NSTAGES) * STAGE_B;
        #pragma unroll
        for (int kh = 0; kh < 4; kh++) {
            // A fragments: 2 comps x 2 m16 tiles
            uint32_t aF[2][2][4];
            #pragma unroll
            for (int t = 0; t < 2; t++) {
                const uint32_t Abase = stage + (2 * t) * TILE_B;
                #pragma unroll
                for (int mt = 0; mt < 2; mt++) {
                    uint32_t addr = Abase + (warpRow * 32 + mt * 16 + rA) * STRIDE +
                                    (kh * 2 + cA) * 16;
                    ldmatrix_x4(aF[t][mt][0], aF[t][mt][1], aF[t][mt][2], aF[t][mt][3], addr);
                }
            }
            // B fragments: 2 comps x 4 n8 tiles
            uint32_t bF[2][4][2];
            #pragma unroll
            for (int t = 0; t < 2; t++) {
                const uint32_t Bbase = stage + (2 * t + 1) * TILE_B;
                #pragma unroll
                for (int pr = 0; pr < 2; pr++) {
                    uint32_t addr = Bbase + (warpCol * 32 + pr * 16 + rB) * STRIDE +
                                    (kh * 2 + cB) * 16;
                    uint32_t r0, r1, r2, r3;
                    ldmatrix_x4(r0, r1, r2, r3, addr);
                    bF[t][pr * 2 + 0][0] = r0; bF[t][pr * 2 + 0][1] = r1;
                    bF[t][pr * 2 + 1][0] = r2; bF[t][pr * 2 + 1][1] = r3;
                }
            }
            // hi*hi -> acc ; hi*lo + lo*hi -> acc2 (grouped, r10 order)
            #pragma unroll
            for (int mt = 0; mt < 2; mt++)
                #pragma unroll
                for (int nt = 0; nt < 4; nt++)
                    mma_f16(acc[mt][nt], aF[0][mt], bF[0][nt]);
            #pragma unroll
            for (int mt = 0; mt < 2; mt++)
                #pragma unroll
                for (int nt = 0; nt < 4; nt++)
                    mma_f16(acc2[mt][nt], aF[0][mt], bF[1][nt]);
            #pragma unroll
            for (int mt = 0; mt < 2; mt++)
                #pragma unroll
                for (int nt = 0; nt < 4; nt++)
                    mma_f16(acc2[mt][nt], aF[1][mt], bF[0][nt]);
        }
    }

    // ---- epilogue ----
    const int gr = lane >> 2;         // row within 8
    const int cc = (lane & 3) * 2;    // col pair

    #pragma unroll
    for (int mt = 0; mt < 2; mt++) {
        #pragma unroll
        for (int nt = 0; nt < 4; nt++) {
            float d[4];
            #pragma unroll
            for (int e = 0; e < 4; e++) d[e] = acc[mt][nt][e] + acc2[mt][nt][e];
            const int col = blockN + warpCol * 32 + nt * 8 + cc;
            const int row0 = blockM + warpRow * 32 + mt * 16 + gr;
            float bv0, bv1;
            if (MODE == 0) {
                bv0 = bias[col];
                bv1 = bias[col + 1];
            } else {
                bv0 = (col < biasN) ? bias[col] : 0.0f;
                bv1 = (col + 1 < biasN) ? bias[col + 1] : 0.0f;
            }
            if (MODE == 0) {
                #pragma unroll
                for (int h = 0; h < 2; h++) {
                    const int row = row0 + h * 8;
                    float v0 = fmaxf(d[2 * h + 0] + bv0, 0.0f);
                    float v1 = fmaxf(d[2 * h + 1] + bv1, 0.0f);
                    __half h0, l0, h1, l1;
                    split2(v0, h0, l0);
                    split2(v1, h1, l1);
                    size_t off = (size_t)row * HIDDEN + col;
                    *(uint32_t*)(o_hi + off) = pack_f16(h0, h1);
                    *(uint32_t*)(o_lo + off) = pack_f16(l0, l1);
                }
            } else {
                #pragma unroll
                for (int h = 0; h < 2; h++) {
                    const int row = row0 + h * 8;
                    float2 v;
                    v.x = d[2 * h + 0] + bv0;
                    v.y = d[2 * h + 1] + bv1;
                    *(float2*)(o_f32 + (size_t)row * NPAD + col) = v;
                }
            }
        }
    }
}

// ---------------------------------------------------------------------------
// Row softmax (reads NPAD-strided logits, first CLASSES cols)
// ---------------------------------------------------------------------------
__inline__ __device__ float warpMax(float v) {
    #pragma unroll
    for (int o = 16; o > 0; o >>= 1) v = fmaxf(v, __shfl_xor_sync(0xffffffffu, v, o));
    return v;
}
__inline__ __device__ float warpSum(float v) {
    #pragma unroll
    for (int o = 16; o > 0; o >>= 1) v += __shfl_xor_sync(0xffffffffu, v, o);
    return v;
}

__global__ __launch_bounds__(256)
void softmax_kernel(const float* __restrict__ logits, float* __restrict__ out) {
    const int row = blockIdx.x;
    const float* lp = logits + (size_t)row * NPAD;
    float* op = out + (size_t)row * CLASSES;

    const int tid = threadIdx.x, lane = tid & 31, warp = tid >> 5;
    __shared__ float red[8];

    float v[4];
    int idx[4], cnt = 0;
    for (int i = tid; i < CLASSES; i += 256) { v[cnt] = lp[i]; idx[cnt] = i; cnt++; }

    float m = -INFINITY;
    for (int t = 0; t < cnt; t++) m = fmaxf(m, v[t]);
    m = warpMax(m);
    if (lane == 0) red[warp] = m;
    __syncthreads();
    m = (lane < 8) ? red[lane] : -INFINITY;
    m = warpMax(m);
    m = __shfl_sync(0xffffffffu, m, 0);

    float s = 0.0f;
    for (int t = 0; t < cnt; t++) { v[t] = __expf(v[t] - m); s += v[t]; }
    s = warpSum(s);
    __syncthreads();
    if (lane == 0) red[warp] = s;
    __syncthreads();
    s = (lane < 8) ? red[lane] : 0.0f;
    s = warpSum(s);
    s = __shfl_sync(0xffffffffu, s, 0);

    const float inv = 1.0f / s;
    for (int t = 0; t < cnt; t++) op[idx[t]] = v[t] * inv;
}

// ---------------------------------------------------------------------------
// Host launch
// ---------------------------------------------------------------------------
extern "C" void kernel_launch(void* const* d_in, const int* in_sizes, int n_in,
                              void* d_out, int out_size) {
    const float* x  = (const float*)d_in[0];
    const float* w1 = (const float*)d_in[1];
    const float* b1 = (const float*)d_in[2];
    const float* w2 = (const float*)d_in[3];
    const float* b2 = (const float*)d_in[4];
    float* out = (float*)d_out;

    __half *xs, *w1s, *w2s, *hs;
    float* logits;
    cudaGetSymbolAddress((void**)&xs,  g_x_s);
    cudaGetSymbolAddress((void**)&w1s, g_w1_s);
    cudaGetSymbolAddress((void**)&w2s, g_w2_s);
    cudaGetSymbolAddress((void**)&hs,  g_h_s);
    cudaGetSymbolAddress((void**)&logits, g_logits);

    const size_t XN  = (size_t)BATCH * INPUT;
    const size_t W1N = (size_t)HIDDEN * INPUT;
    const size_t W2N = (size_t)NPAD * INPUT;
    const size_t HN  = (size_t)BATCH * HIDDEN;

    __half* x_c[2]  = {xs, xs + XN};
    __half* w1_c[2] = {w1s, w1s + W1N};
    __half* w2_c[2] = {w2s, w2s + W2N};
    __half* h_c[2]  = {hs, hs + HN};

    // One merged split launch for x, w1, w2
    {
        int n4x = (int)(XN / 4);
        int n4w1 = (int)(W1N / 4);
        int n4w2p = (int)(W2N / 4);
        int total = n4x + n4w1 + n4w2p;
        split2_all_kernel<<<(total + 255) / 256, 256>>>(
            (const float4*)x, (const float4*)w1, (const float4*)w2,
            x_c[0], x_c[1], w1_c[0], w1_c[1], w2_c[0], w2_c[1],
            n4x, n4w1, n4w2p);
    }

    cudaFuncSetAttribute(gemm_kernel<0>, cudaFuncAttributeMaxDynamicSharedMemorySize, DYN_SMEM);
    cudaFuncSetAttribute(gemm_kernel<1>, cudaFuncAttributeMaxDynamicSharedMemorySize, DYN_SMEM);

    // GEMM1: hidden = relu(x @ w1^T + b1), re-split into 2 fp16 components
    {
        dim3 grid(HIDDEN / BN, BATCH / BM);
        gemm_kernel<0><<<grid, GTHREADS, DYN_SMEM>>>(
            x_c[0], x_c[1], w1_c[0], w1_c[1],
            b1, HIDDEN, h_c[0], h_c[1], nullptr);
    }
    // GEMM2: logits = hidden @ w2^T + b2 (fp32, NPAD-wide scratch)
    {
        dim3 grid(NPAD / BN, BATCH / BM);
        gemm_kernel<1><<<grid, GTHREADS, DYN_SMEM>>>(
            h_c[0], h_c[1], w2_c[0], w2_c[1],
            b2, CLASSES, nullptr, nullptr, logits);
    }
    softmax_kernel<<<BATCH, 256>>>(logits, out);
}